// round 13
// baseline (speedup 1.0000x reference)
#include <cuda_runtime.h>
#include <cuda_fp16.h>
#include <cstdint>

#define BATCH 8
#define NPTS  4096
#define MROWS 32768
#define FD    512

// GEMM tiling
#define BM 128
#define BN 64
#define BK 64
#define CHUNK_A 16384                   // A: 128 rows x 64 k x 2B
#define CHUNK_B 8192                    // B: 64 cols x 64 k x 2B
#define STAGE_BYTES (CHUNK_A + CHUNK_B) // 24576
#define NSTAGE 3
#define SMEM_TOTAL (NSTAGE * STAGE_BYTES)  // 73728
#define MBLK_STRIDE (8 * 16384)         // fragment layout: 8 chunks per 128-row/col block

// ---------------------------------------------------------------------------
// Device scratch (fragment-layout fp16 operands)
// ---------------------------------------------------------------------------
__device__ float  g_feat[MROWS * 12];
__device__ __half g_lat[MROWS * FD];    // A-fragment layout
__device__ __half g_h[MROWS * FD];      // A-fragment layout
__device__ float  g_std1[MROWS];
__device__ float  g_std2[MROWS];
__device__ __half g_w1T[FD * FD];       // B-fragment layout
__device__ __half g_wrT[FD * FD];       // B-fragment layout

// ---------------------------------------------------------------------------
// Helpers
// ---------------------------------------------------------------------------
__device__ __forceinline__ uint32_t smem_u32(const void* p) {
    uint32_t a;
    asm("{ .reg .u64 t; cvta.to.shared.u64 t, %1; cvt.u32.u64 %0, t; }" : "=r"(a) : "l"(p));
    return a;
}

__device__ __forceinline__ void bulk_cp(uint32_t dst, const void* src, uint32_t bytes, uint32_t mbar) {
    asm volatile(
        "cp.async.bulk.shared::cluster.global.mbarrier::complete_tx::bytes [%0], [%1], %2, [%3];"
        :: "r"(dst), "l"(src), "r"(bytes), "r"(mbar) : "memory");
}

#define MB_INIT(mb, c)    asm volatile("mbarrier.init.shared.b64 [%0], %1;" :: "r"(mb), "r"(c) : "memory")
#define MB_EXPECT(mb, tx) asm volatile("mbarrier.arrive.expect_tx.shared.b64 _, [%0], %1;" :: "r"(mb), "r"(tx) : "memory")

__device__ __forceinline__ void mb_wait_parity(uint32_t mb, uint32_t par) {
    uint32_t done;
    asm volatile(
        "{\n\t.reg .pred p;\n\tmbarrier.try_wait.parity.acquire.cta.shared::cta.b64 p, [%1], %2;\n\tselp.b32 %0, 1, 0, p;\n\t}"
        : "=r"(done) : "r"(mb), "r"(par) : "memory");
    if (!done) {
        asm volatile(
            "{\n\t.reg .pred P1;\n\tWL_%=:\n\t"
            "mbarrier.try_wait.parity.acquire.cta.shared::cta.b64 P1, [%0], %1, 0x989680;\n\t"
            "@P1 bra.uni WD_%=;\n\tbra.uni WL_%=;\n\tWD_%=:\n\t}"
            :: "r"(mb), "r"(par) : "memory");
    }
}

#define LDS128(r0, r1, r2, r3, addr) \
    asm volatile("ld.shared.v4.b32 {%0,%1,%2,%3}, [%4];" \
        : "=r"(r0), "=r"(r1), "=r"(r2), "=r"(r3) : "r"(addr))

__device__ __forceinline__ void mma_f16(float* c, const uint32_t* a, const uint32_t* b) {
    asm volatile(
        "mma.sync.aligned.m16n8k16.row.col.f32.f16.f16.f32 "
        "{%0,%1,%2,%3}, {%4,%5,%6,%7}, {%8,%9}, {%0,%1,%2,%3};"
        : "+f"(c[0]), "+f"(c[1]), "+f"(c[2]), "+f"(c[3])
        : "r"(a[0]), "r"(a[1]), "r"(a[2]), "r"(a[3]), "r"(b[0]), "r"(b[1]));
}

__device__ __forceinline__ uint32_t h2u(__half2 h) { return *(uint32_t*)&h; }

// ---------------------------------------------------------------------------
// kNN + local covariance
// ---------------------------------------------------------------------------
__global__ __launch_bounds__(256) void knn_feat_kernel(
    const float* __restrict__ rp, float* __restrict__ feat)
{
    __shared__ float px[NPTS], py[NPTS], pz[NPTS];
    const int b = blockIdx.y;
    const float* base = rp + b * 3 * NPTS;
    for (int i = threadIdx.x; i < NPTS; i += 256) {
        px[i] = base[i]; py[i] = base[NPTS + i]; pz[i] = base[2 * NPTS + i];
    }
    __syncthreads();

    const int n = blockIdx.x * 256 + threadIdx.x;
    const float xi = px[n], yi = py[n], zi = pz[n];
    const float xxi = xi * xi + yi * yi + zi * zi;

    float bestv = -1e30f; int bestj = 0;
    for (int j = 0; j < NPTS; j++) {
        const float xj = px[j], yj = py[j], zj = pz[j];
        const float d = 2.0f * (xi * xj + yi * yj + zi * zj) - xxi - (xj * xj + yj * yj + zj * zj);
        if (j != n && d > bestv) { bestv = d; bestj = j; }
    }
    const float nx = px[bestj], ny = py[bestj], nz = pz[bestj];
    float* f = feat + (size_t)(b * NPTS + n) * 12;
    f[0] = xi;      f[1] = yi;      f[2] = zi;
    f[3] = xi * nx; f[4] = xi * ny; f[5] = xi * nz;
    f[6] = yi * nx; f[7] = yi * ny; f[8] = yi * nz;
    f[9] = zi * nx; f[10] = zi * ny; f[11] = zi * nz;
}

// ---------------------------------------------------------------------------
// latent fp32 [m][k] -> A-fragment fp16 layout
// ---------------------------------------------------------------------------
__global__ __launch_bounds__(256) void conv_frag_kernel(
    const float* __restrict__ x, __half* __restrict__ o)
{
    const int u = blockIdx.x * 256 + threadIdx.x;
    const int lane = u & 31, mtb = (u >> 5) & 7, kk = (u >> 8) & 3;
    const int kch = (u >> 10) & 7, mblk = u >> 13;
    const int m = mblk * 128 + mtb * 16 + (lane >> 2);
    const int k = kch * 64 + kk * 16 + (lane & 3) * 2;
    const float* s0 = x + (size_t)m * FD + k;
    const float* s1 = s0 + 8 * FD;
    float2 f00 = *(const float2*)(s0);
    float2 f10 = *(const float2*)(s1);
    float2 f01 = *(const float2*)(s0 + 8);
    float2 f11 = *(const float2*)(s1 + 8);
    uint4 q;
    q.x = h2u(__floats2half2_rn(f00.x, f00.y));
    q.y = h2u(__floats2half2_rn(f10.x, f10.y));
    q.z = h2u(__floats2half2_rn(f01.x, f01.y));
    q.w = h2u(__floats2half2_rn(f11.x, f11.y));
    *(uint4*)((char*)o + (size_t)u * 16) = q;
}

// ---------------------------------------------------------------------------
// W fp32 [k][n] -> B-fragment fp16 layout
// ---------------------------------------------------------------------------
__global__ __launch_bounds__(256) void transW_frag_kernel(
    const float* __restrict__ W, __half* __restrict__ o)
{
    const int u = blockIdx.x * 256 + threadIdx.x;
    const int lane = u & 31, cb = (u >> 5) & 7, kk = (u >> 8) & 3;
    const int kch = (u >> 10) & 7, nblk = u >> 13;
    const int n = nblk * 128 + cb * 16 + (lane >> 2);
    const int k = kch * 64 + kk * 16 + (lane & 3) * 2;
    const float* s = W + (size_t)k * FD + n;
    uint4 q;
    q.x = h2u(__floats2half2_rn(s[0],          s[FD]));
    q.y = h2u(__floats2half2_rn(s[8 * FD],     s[9 * FD]));
    q.z = h2u(__floats2half2_rn(s[8],          s[FD + 8]));
    q.w = h2u(__floats2half2_rn(s[8 * FD + 8], s[9 * FD + 8]));
    *(uint4*)((char*)o + (size_t)u * 16) = q;
}

// ---------------------------------------------------------------------------
// out[row] = (prev ? prev[row] : 0) + b2[0]
// ---------------------------------------------------------------------------
__global__ __launch_bounds__(256) void init_out_kernel(
    const float* __restrict__ prev, const float* __restrict__ b2, float* __restrict__ out)
{
    const int i = blockIdx.x * 256 + threadIdx.x;
    out[i] = (prev ? prev[i] : 0.0f) + b2[0];
}

// ---------------------------------------------------------------------------
// fp16 mma.sync GEMM, BM=128 x BN=64, warp tile 32x32, 3 CTAs/SM.
//  MODE 0:  H = relu(C + A2@Wtail + bias) -> outH (A-fragment layout)
//  MODE 1:  v = relu(C + A + bias); atomicAdd(dotOut, v@w2)
// ---------------------------------------------------------------------------
template <int MODE>
__global__ __launch_bounds__(256, 3) void gemm_mma_kernel(
    const __half* __restrict__ A,       // A-fragment layout
    const __half* __restrict__ B,       // B-fragment layout
    const float* __restrict__ bias,
    const float* __restrict__ A2, const int K2, const float* __restrict__ Wtail,
    __half* __restrict__ outH,
    const float* __restrict__ w2, float* __restrict__ dotOut)
{
    extern __shared__ __align__(128) char dsm[];
    __shared__ __align__(8) uint64_t s_mbar[NSTAGE];
    const uint32_t sbase = smem_u32(dsm);
    const uint32_t mb = smem_u32(s_mbar);

    const int tid = threadIdx.x;
    const int m0 = blockIdx.y * BM;
    const int warp = tid >> 5, lane = tid & 31;
    const int warp_m = warp >> 1;          // 0..3 -> 32 rows each
    const int warp_n = warp & 1;           // 0..1 -> 32 cols each

    if (tid == 0) {
        #pragma unroll
        for (int s = 0; s < NSTAGE; s++) MB_INIT(mb + 8 * s, 1);
    }
    __syncthreads();

    const char* Asrc = (const char*)A + (size_t)blockIdx.y * MBLK_STRIDE;
    // B: 64-col slice of a 128-col fragment block
    const char* Bsrc = (const char*)B + (size_t)(blockIdx.x >> 1) * MBLK_STRIDE
                       + (blockIdx.x & 1) * 2048;

    auto issue = [&](int ch) {
        const int s = ch % NSTAGE;
        const uint32_t st = sbase + s * STAGE_BYTES;
        MB_EXPECT(mb + 8 * s, STAGE_BYTES);
        bulk_cp(st, Asrc + (size_t)ch * 16384, CHUNK_A, mb + 8 * s);
        #pragma unroll
        for (int kk = 0; kk < 4; kk++)
            bulk_cp(st + CHUNK_A + kk * 2048,
                    Bsrc + (size_t)ch * 16384 + kk * 4096, 2048, mb + 8 * s);
    };

    if (tid == 0) { issue(0); issue(1); }

    // fragment LDS offsets within a kk-block
    uint32_t aoff[2], boff[2];
    #pragma unroll
    for (int mt = 0; mt < 2; mt++)
        aoff[mt] = (uint32_t)(((warp_m * 2 + mt) * 32 + lane) * 16);
    #pragma unroll
    for (int pr = 0; pr < 2; pr++)
        boff[pr] = (uint32_t)(((warp_n * 2 + pr) * 32 + lane) * 16);

    float c[2][4][4];
    #pragma unroll
    for (int i = 0; i < 2; i++)
        #pragma unroll
        for (int j = 0; j < 4; j++)
            #pragma unroll
            for (int q = 0; q < 4; q++) c[i][j][q] = 0.0f;

    auto compute = [&](int s) {
        const uint32_t stA = sbase + s * STAGE_BYTES;
        const uint32_t stB = stA + CHUNK_A;
        #pragma unroll
        for (int kk = 0; kk < 4; kk++) {
            uint32_t a[2][4], bf[4][2];
            #pragma unroll
            for (int mt = 0; mt < 2; mt++)
                LDS128(a[mt][0], a[mt][1], a[mt][2], a[mt][3],
                       stA + (uint32_t)(kk * 4096) + aoff[mt]);
            #pragma unroll
            for (int pr = 0; pr < 2; pr++) {
                uint32_t r0, r1, r2, r3;
                LDS128(r0, r1, r2, r3, stB + (uint32_t)(kk * 2048) + boff[pr]);
                bf[2*pr][0] = r0; bf[2*pr][1] = r1;
                bf[2*pr+1][0] = r2; bf[2*pr+1][1] = r3;
            }
            #pragma unroll
            for (int mt = 0; mt < 2; mt++)
                #pragma unroll
                for (int nt = 0; nt < 4; nt++)
                    mma_f16(c[mt][nt], a[mt], bf[nt]);
        }
    };

    #pragma unroll 1
    for (int ch = 0; ch < FD / BK; ch++) {
        const int s = ch % NSTAGE;
        mb_wait_parity(mb + 8 * s, (ch / NSTAGE) & 1);
        __syncthreads();
        if (tid == 0 && ch + 2 < FD / BK) issue(ch + 2);
        compute(s);
    }

    // ---- epilogue ----
    const int qrow = lane >> 2;
    const int qcol = (lane & 3) * 2;
    const int kch_e = blockIdx.x;          // BN == chunk width (64)

    if (MODE == 0) {
        #pragma unroll
        for (int mt = 0; mt < 2; mt++) {
            const int rowA = m0 + warp_m * 32 + mt * 16 + qrow;
            const int rowB = rowA + 8;

            float a2A[12], a2B[12];
            for (int k = 0; k < K2; k++) {
                a2A[k] = __ldg(A2 + (size_t)rowA * K2 + k);
                a2B[k] = __ldg(A2 + (size_t)rowB * K2 + k);
            }

            float vA[4][2], vB[4][2];
            #pragma unroll
            for (int nt = 0; nt < 4; nt++) {
                const int colg = blockIdx.x * BN + warp_n * 32 + nt * 8 + qcol;
                const float b0 = __ldg(bias + colg), b1 = __ldg(bias + colg + 1);
                float v0 = c[mt][nt][0] + b0, v1 = c[mt][nt][1] + b1;
                float v2 = c[mt][nt][2] + b0, v3 = c[mt][nt][3] + b1;
                for (int k = 0; k < K2; k++) {
                    const float w0 = __ldg(Wtail + (size_t)k * FD + colg);
                    const float w1 = __ldg(Wtail + (size_t)k * FD + colg + 1);
                    v0 += a2A[k] * w0; v1 += a2A[k] * w1;
                    v2 += a2B[k] * w0; v3 += a2B[k] * w1;
                }
                vA[nt][0] = fmaxf(v0, 0.0f); vA[nt][1] = fmaxf(v1, 0.0f);
                vB[nt][0] = fmaxf(v2, 0.0f); vB[nt][1] = fmaxf(v3, 0.0f);
            }
            // store in A-fragment layout
            #pragma unroll
            for (int np = 0; np < 2; np++) {
                const int kkx = warp_n * 2 + np;
                const size_t off =
                    (((((size_t)blockIdx.y * 8 + kch_e) * 4 + kkx) * 8
                      + (warp_m * 2 + mt)) * 32 + lane) * 16;
                uint4 q;
                q.x = h2u(__floats2half2_rn(vA[2*np][0],   vA[2*np][1]));
                q.y = h2u(__floats2half2_rn(vB[2*np][0],   vB[2*np][1]));
                q.z = h2u(__floats2half2_rn(vA[2*np+1][0], vA[2*np+1][1]));
                q.w = h2u(__floats2half2_rn(vB[2*np+1][0], vB[2*np+1][1]));
                *(uint4*)((char*)outH + off) = q;
            }
        }
    } else {
        #pragma unroll
        for (int mt = 0; mt < 2; mt++) {
            const int rowA = m0 + warp_m * 32 + mt * 16 + qrow;
            const int rowB = rowA + 8;

            uint4 rf[2];
            #pragma unroll
            for (int np = 0; np < 2; np++) {
                const int kkx = warp_n * 2 + np;
                const size_t off =
                    (((((size_t)blockIdx.y * 8 + kch_e) * 4 + kkx) * 8
                      + (warp_m * 2 + mt)) * 32 + lane) * 16;
                rf[np] = *(const uint4*)((const char*)A + off);
            }
            const uint32_t rw[4][2] = {
                {rf[0].x, rf[0].y}, {rf[0].z, rf[0].w},
                {rf[1].x, rf[1].y}, {rf[1].z, rf[1].w}};

            float sA = 0.0f, sB = 0.0f;
            #pragma unroll
            for (int nt = 0; nt < 4; nt++) {
                const int colg = blockIdx.x * BN + warp_n * 32 + nt * 8 + qcol;
                const float b0 = __ldg(bias + colg), b1 = __ldg(bias + colg + 1);
                float2 hA = __half22float2(*(const __half2*)&rw[nt][0]);
                float2 hB = __half22float2(*(const __half2*)&rw[nt][1]);
                float v0 = c[mt][nt][0] + b0 + hA.x;
                float v1 = c[mt][nt][1] + b1 + hA.y;
                float v2 = c[mt][nt][2] + b0 + hB.x;
                float v3 = c[mt][nt][3] + b1 + hB.y;
                v0 = fmaxf(v0, 0.0f); v1 = fmaxf(v1, 0.0f);
                v2 = fmaxf(v2, 0.0f); v3 = fmaxf(v3, 0.0f);
                const float w0 = __ldg(w2 + colg), w1 = __ldg(w2 + colg + 1);
                sA += v0 * w0 + v1 * w1;
                sB += v2 * w0 + v3 * w1;
            }
            sA += __shfl_xor_sync(0xFFFFFFFFu, sA, 1);
            sA += __shfl_xor_sync(0xFFFFFFFFu, sA, 2);
            sB += __shfl_xor_sync(0xFFFFFFFFu, sB, 1);
            sB += __shfl_xor_sync(0xFFFFFFFFu, sB, 2);
            if ((lane & 3) == 0) {
                atomicAdd(dotOut + rowA, sA);
                atomicAdd(dotOut + rowB, sB);
            }
        }
    }
}

// ---------------------------------------------------------------------------
// Host orchestration
// ---------------------------------------------------------------------------
extern "C" void kernel_launch(void* const* d_in, const int* in_sizes, int n_in,
                              void* d_out, int out_size)
{
    const float* latent = (const float*)d_in[0];
    const float* rp     = (const float*)d_in[1];
    const float* w1[3] = {(const float*)d_in[2],  (const float*)d_in[8],  (const float*)d_in[14]};
    const float* b1[3] = {(const float*)d_in[3],  (const float*)d_in[9],  (const float*)d_in[15]};
    const float* wr[3] = {(const float*)d_in[4],  (const float*)d_in[10], (const float*)d_in[16]};
    const float* br[3] = {(const float*)d_in[5],  (const float*)d_in[11], (const float*)d_in[17]};
    const float* w2[3] = {(const float*)d_in[6],  (const float*)d_in[12], (const float*)d_in[18]};
    const float* b2[3] = {(const float*)d_in[7],  (const float*)d_in[13], (const float*)d_in[19]};

    float *feat, *std1, *std2;
    __half *lat, *h, *w1T, *wrT;
    cudaGetSymbolAddress((void**)&feat, g_feat);
    cudaGetSymbolAddress((void**)&lat,  g_lat);
    cudaGetSymbolAddress((void**)&h,    g_h);
    cudaGetSymbolAddress((void**)&std1, g_std1);
    cudaGetSymbolAddress((void**)&std2, g_std2);
    cudaGetSymbolAddress((void**)&w1T,  g_w1T);
    cudaGetSymbolAddress((void**)&wrT,  g_wrT);

    float* out = (float*)d_out;

    cudaFuncSetAttribute(gemm_mma_kernel<0>, cudaFuncAttributeMaxDynamicSharedMemorySize, SMEM_TOTAL);
    cudaFuncSetAttribute(gemm_mma_kernel<1>, cudaFuncAttributeMaxDynamicSharedMemorySize, SMEM_TOTAL);

    const dim3 ggrid(FD / BN, MROWS / BM);   // (8, 256)

    conv_frag_kernel<<<MROWS * FD / 8 / 256, 256>>>(latent, lat);
    knn_feat_kernel<<<dim3(NPTS / 256, BATCH), 256>>>(rp, feat);

    const float* stdprev[3] = {nullptr, std1, std2};
    const float* a2s[3]     = {feat, std1, std2};
    const int    k2s[3]     = {12, 1, 1};
    float*       stdout_[3] = {std1, std2, out};

    for (int s = 0; s < 3; s++) {
        transW_frag_kernel<<<FD * FD / 8 / 256, 256>>>(w1[s], w1T);
        gemm_mma_kernel<0><<<ggrid, 256, SMEM_TOTAL>>>(
            lat, w1T, b1[s],
            a2s[s], k2s[s], w1[s] + (size_t)FD * FD,
            h, nullptr, nullptr);
        transW_frag_kernel<<<FD * FD / 8 / 256, 256>>>(wr[s], wrT);
        init_out_kernel<<<MROWS / 256, 256>>>(stdprev[s], b2[s], stdout_[s]);
        gemm_mma_kernel<1><<<ggrid, 256, SMEM_TOTAL>>>(
            h, wrT, br[s],
            nullptr, 0, nullptr,
            nullptr, w2[s], stdout_[s]);
    }
}

// round 15
// speedup vs baseline: 1.4317x; 1.4317x over previous
#include <cuda_runtime.h>
#include <cuda_fp16.h>
#include <cstdint>

#define BATCH 8
#define NPTS  4096
#define MROWS 32768
#define FD    512

// GEMM tiling
#define BM 128
#define BN 64
#define BK 64
#define CHUNK_B 8192                    // B: 64 cols x 64 k x 2B (smem)
#define STAGE_BYTES CHUNK_B
#define NSTAGE 4
#define SMEM_TOTAL (NSTAGE * STAGE_BYTES)  // 32768
#define MBLK_STRIDE (8 * 16384)         // fragment layout: 8 chunks per 128-row/col block

// ---------------------------------------------------------------------------
// Device scratch (fragment-layout fp16 operands)
// ---------------------------------------------------------------------------
__device__ float  g_feat[MROWS * 12];
__device__ __half g_lat[MROWS * FD];    // A-fragment layout
__device__ __half g_h[MROWS * FD];      // A-fragment layout
__device__ float  g_std1[MROWS];
__device__ float  g_std2[MROWS];
__device__ __half g_w1T[FD * FD];       // B-fragment layout
__device__ __half g_wrT[FD * FD];       // B-fragment layout

// ---------------------------------------------------------------------------
// Helpers
// ---------------------------------------------------------------------------
__device__ __forceinline__ uint32_t smem_u32(const void* p) {
    uint32_t a;
    asm("{ .reg .u64 t; cvta.to.shared.u64 t, %1; cvt.u32.u64 %0, t; }" : "=r"(a) : "l"(p));
    return a;
}

__device__ __forceinline__ void bulk_cp(uint32_t dst, const void* src, uint32_t bytes, uint32_t mbar) {
    asm volatile(
        "cp.async.bulk.shared::cluster.global.mbarrier::complete_tx::bytes [%0], [%1], %2, [%3];"
        :: "r"(dst), "l"(src), "r"(bytes), "r"(mbar) : "memory");
}

#define MB_INIT(mb, c)    asm volatile("mbarrier.init.shared.b64 [%0], %1;" :: "r"(mb), "r"(c) : "memory")
#define MB_EXPECT(mb, tx) asm volatile("mbarrier.arrive.expect_tx.shared.b64 _, [%0], %1;" :: "r"(mb), "r"(tx) : "memory")

__device__ __forceinline__ void mb_wait_parity(uint32_t mb, uint32_t par) {
    uint32_t done;
    asm volatile(
        "{\n\t.reg .pred p;\n\tmbarrier.try_wait.parity.acquire.cta.shared::cta.b64 p, [%1], %2;\n\tselp.b32 %0, 1, 0, p;\n\t}"
        : "=r"(done) : "r"(mb), "r"(par) : "memory");
    if (!done) {
        asm volatile(
            "{\n\t.reg .pred P1;\n\tWL_%=:\n\t"
            "mbarrier.try_wait.parity.acquire.cta.shared::cta.b64 P1, [%0], %1, 0x989680;\n\t"
            "@P1 bra.uni WD_%=;\n\tbra.uni WL_%=;\n\tWD_%=:\n\t}"
            :: "r"(mb), "r"(par) : "memory");
    }
}

#define LDS128(r0, r1, r2, r3, addr) \
    asm volatile("ld.shared.v4.b32 {%0,%1,%2,%3}, [%4];" \
        : "=r"(r0), "=r"(r1), "=r"(r2), "=r"(r3) : "r"(addr))

__device__ __forceinline__ void mma_f16(float* c, const uint32_t* a, const uint32_t* b) {
    asm volatile(
        "mma.sync.aligned.m16n8k16.row.col.f32.f16.f16.f32 "
        "{%0,%1,%2,%3}, {%4,%5,%6,%7}, {%8,%9}, {%0,%1,%2,%3};"
        : "+f"(c[0]), "+f"(c[1]), "+f"(c[2]), "+f"(c[3])
        : "r"(a[0]), "r"(a[1]), "r"(a[2]), "r"(a[3]), "r"(b[0]), "r"(b[1]));
}

__device__ __forceinline__ uint32_t h2u(__half2 h) { return *(uint32_t*)&h; }

// ---------------------------------------------------------------------------
// kNN + local covariance
// ---------------------------------------------------------------------------
__global__ __launch_bounds__(256) void knn_feat_kernel(
    const float* __restrict__ rp, float* __restrict__ feat)
{
    __shared__ float px[NPTS], py[NPTS], pz[NPTS];
    const int b = blockIdx.y;
    const float* base = rp + b * 3 * NPTS;
    for (int i = threadIdx.x; i < NPTS; i += 256) {
        px[i] = base[i]; py[i] = base[NPTS + i]; pz[i] = base[2 * NPTS + i];
    }
    __syncthreads();

    const int n = blockIdx.x * 256 + threadIdx.x;
    const float xi = px[n], yi = py[n], zi = pz[n];
    const float xxi = xi * xi + yi * yi + zi * zi;

    float bestv = -1e30f; int bestj = 0;
    for (int j = 0; j < NPTS; j++) {
        const float xj = px[j], yj = py[j], zj = pz[j];
        const float d = 2.0f * (xi * xj + yi * yj + zi * zj) - xxi - (xj * xj + yj * yj + zj * zj);
        if (j != n && d > bestv) { bestv = d; bestj = j; }
    }
    const float nx = px[bestj], ny = py[bestj], nz = pz[bestj];
    float* f = feat + (size_t)(b * NPTS + n) * 12;
    f[0] = xi;      f[1] = yi;      f[2] = zi;
    f[3] = xi * nx; f[4] = xi * ny; f[5] = xi * nz;
    f[6] = yi * nx; f[7] = yi * ny; f[8] = yi * nz;
    f[9] = zi * nx; f[10] = zi * ny; f[11] = zi * nz;
}

// ---------------------------------------------------------------------------
// latent fp32 [m][k] -> A-fragment fp16 layout
// ---------------------------------------------------------------------------
__global__ __launch_bounds__(256) void conv_frag_kernel(
    const float* __restrict__ x, __half* __restrict__ o)
{
    const int u = blockIdx.x * 256 + threadIdx.x;
    const int lane = u & 31, mtb = (u >> 5) & 7, kk = (u >> 8) & 3;
    const int kch = (u >> 10) & 7, mblk = u >> 13;
    const int m = mblk * 128 + mtb * 16 + (lane >> 2);
    const int k = kch * 64 + kk * 16 + (lane & 3) * 2;
    const float* s0 = x + (size_t)m * FD + k;
    const float* s1 = s0 + 8 * FD;
    float2 f00 = *(const float2*)(s0);
    float2 f10 = *(const float2*)(s1);
    float2 f01 = *(const float2*)(s0 + 8);
    float2 f11 = *(const float2*)(s1 + 8);
    uint4 q;
    q.x = h2u(__floats2half2_rn(f00.x, f00.y));
    q.y = h2u(__floats2half2_rn(f10.x, f10.y));
    q.z = h2u(__floats2half2_rn(f01.x, f01.y));
    q.w = h2u(__floats2half2_rn(f11.x, f11.y));
    *(uint4*)((char*)o + (size_t)u * 16) = q;
}

// ---------------------------------------------------------------------------
// W fp32 [k][n] -> B-fragment fp16 layout
// ---------------------------------------------------------------------------
__global__ __launch_bounds__(256) void transW_frag_kernel(
    const float* __restrict__ W, __half* __restrict__ o)
{
    const int u = blockIdx.x * 256 + threadIdx.x;
    const int lane = u & 31, cb = (u >> 5) & 7, kk = (u >> 8) & 3;
    const int kch = (u >> 10) & 7, nblk = u >> 13;
    const int n = nblk * 128 + cb * 16 + (lane >> 2);
    const int k = kch * 64 + kk * 16 + (lane & 3) * 2;
    const float* s = W + (size_t)k * FD + n;
    uint4 q;
    q.x = h2u(__floats2half2_rn(s[0],          s[FD]));
    q.y = h2u(__floats2half2_rn(s[8 * FD],     s[9 * FD]));
    q.z = h2u(__floats2half2_rn(s[8],          s[FD + 8]));
    q.w = h2u(__floats2half2_rn(s[8 * FD + 8], s[9 * FD + 8]));
    *(uint4*)((char*)o + (size_t)u * 16) = q;
}

// ---------------------------------------------------------------------------
// out[row] = (prev ? prev[row] : 0) + b2[0]
// ---------------------------------------------------------------------------
__global__ __launch_bounds__(256) void init_out_kernel(
    const float* __restrict__ prev, const float* __restrict__ b2, float* __restrict__ out)
{
    const int i = blockIdx.x * 256 + threadIdx.x;
    out[i] = (prev ? prev[i] : 0.0f) + b2[0];
}

// ---------------------------------------------------------------------------
// fp16 mma.sync GEMM, BM=128 x BN=64, warp tile 32x32, 3 CTAs/SM.
// A fragments loaded directly from gmem (L2); only B staged in smem.
//  MODE 0:  H = relu(C + A2@Wtail + bias) -> outH (A-fragment layout)
//  MODE 1:  v = relu(C + A + bias); atomicAdd(dotOut, v@w2)
// ---------------------------------------------------------------------------
template <int MODE>
__global__ __launch_bounds__(256, 3) void gemm_mma_kernel(
    const __half* __restrict__ A,       // A-fragment layout
    const __half* __restrict__ B,       // B-fragment layout
    const float* __restrict__ bias,
    const float* __restrict__ A2, const int K2, const float* __restrict__ Wtail,
    __half* __restrict__ outH,
    const float* __restrict__ w2, float* __restrict__ dotOut)
{
    extern __shared__ __align__(128) char dsm[];
    __shared__ __align__(8) uint64_t s_mbar[NSTAGE];
    const uint32_t sbase = smem_u32(dsm);
    const uint32_t mb = smem_u32(s_mbar);

    const int tid = threadIdx.x;
    const int m0 = blockIdx.y * BM;
    const int warp = tid >> 5, lane = tid & 31;
    const int warp_m = warp >> 1;          // 0..3 -> 32 rows each
    const int warp_n = warp & 1;           // 0..1 -> 32 cols each

    if (tid == 0) {
        #pragma unroll
        for (int s = 0; s < NSTAGE; s++) MB_INIT(mb + 8 * s, 1);
    }
    __syncthreads();

    const char* Asrc = (const char*)A + (size_t)blockIdx.y * MBLK_STRIDE;
    const char* Bsrc = (const char*)B + (size_t)(blockIdx.x >> 1) * MBLK_STRIDE
                       + (blockIdx.x & 1) * 2048;

    auto issue = [&](int ch) {
        const int s = ch % NSTAGE;
        const uint32_t st = sbase + s * STAGE_BYTES;
        MB_EXPECT(mb + 8 * s, STAGE_BYTES);
        #pragma unroll
        for (int kk = 0; kk < 4; kk++)
            bulk_cp(st + kk * 2048,
                    Bsrc + (size_t)ch * 16384 + kk * 4096, 2048, mb + 8 * s);
    };

    if (tid == 0) { issue(0); issue(1); issue(2); }

    // B fragment LDS offsets within a kk-block
    uint32_t boff[2];
    #pragma unroll
    for (int pr = 0; pr < 2; pr++)
        boff[pr] = (uint32_t)(((warp_n * 2 + pr) * 32 + lane) * 16);

    // A fragment gmem offset within a kk-block (bytes)
    const uint32_t aByte0 = (uint32_t)((warp_m * 2) * 512 + lane * 16);

    float c[2][4][4];
    #pragma unroll
    for (int i = 0; i < 2; i++)
        #pragma unroll
        for (int j = 0; j < 4; j++)
            #pragma unroll
            for (int q = 0; q < 4; q++) c[i][j][q] = 0.0f;

    auto compute = [&](int s, const char* Achunk) {
        const uint32_t stB = sbase + s * STAGE_BYTES;
        // preload A fragments for kk=0,1 (register double buffer)
        uint4 aF[2][2];
        #pragma unroll
        for (int p = 0; p < 2; p++)
            #pragma unroll
            for (int mt = 0; mt < 2; mt++)
                aF[p][mt] = __ldg((const uint4*)(Achunk + p * 4096 + aByte0 + mt * 512));
        #pragma unroll
        for (int kk = 0; kk < 4; kk++) {
            const int p = kk & 1;
            uint32_t bf[4][2];
            #pragma unroll
            for (int pr = 0; pr < 2; pr++) {
                uint32_t r0, r1, r2, r3;
                LDS128(r0, r1, r2, r3, stB + (uint32_t)(kk * 2048) + boff[pr]);
                bf[2*pr][0] = r0; bf[2*pr][1] = r1;
                bf[2*pr+1][0] = r2; bf[2*pr+1][1] = r3;
            }
            #pragma unroll
            for (int mt = 0; mt < 2; mt++) {
                const uint32_t a[4] = {aF[p][mt].x, aF[p][mt].y, aF[p][mt].z, aF[p][mt].w};
                #pragma unroll
                for (int nt = 0; nt < 4; nt++)
                    mma_f16(c[mt][nt], a, bf[nt]);
            }
            if (kk < 2) {
                #pragma unroll
                for (int mt = 0; mt < 2; mt++)
                    aF[p][mt] = __ldg((const uint4*)(Achunk + (kk + 2) * 4096 + aByte0 + mt * 512));
            }
        }
    };

    #pragma unroll 1
    for (int ch = 0; ch < FD / BK; ch++) {
        const int s = ch % NSTAGE;
        mb_wait_parity(mb + 8 * s, (ch / NSTAGE) & 1);
        __syncthreads();
        if (tid == 0 && ch + 3 < FD / BK) issue(ch + 3);
        compute(s, Asrc + (size_t)ch * 16384);
    }

    // ---- epilogue ----
    const int qrow = lane >> 2;
    const int qcol = (lane & 3) * 2;
    const int kch_e = blockIdx.x;          // BN == chunk width (64)

    if (MODE == 0) {
        #pragma unroll
        for (int mt = 0; mt < 2; mt++) {
            const int rowA = m0 + warp_m * 32 + mt * 16 + qrow;
            const int rowB = rowA + 8;

            float a2A[12], a2B[12];
            for (int k = 0; k < K2; k++) {
                a2A[k] = __ldg(A2 + (size_t)rowA * K2 + k);
                a2B[k] = __ldg(A2 + (size_t)rowB * K2 + k);
            }

            float vA[4][2], vB[4][2];
            #pragma unroll
            for (int nt = 0; nt < 4; nt++) {
                const int colg = blockIdx.x * BN + warp_n * 32 + nt * 8 + qcol;
                const float b0 = __ldg(bias + colg), b1 = __ldg(bias + colg + 1);
                float v0 = c[mt][nt][0] + b0, v1 = c[mt][nt][1] + b1;
                float v2 = c[mt][nt][2] + b0, v3 = c[mt][nt][3] + b1;
                for (int k = 0; k < K2; k++) {
                    const float w0 = __ldg(Wtail + (size_t)k * FD + colg);
                    const float w1 = __ldg(Wtail + (size_t)k * FD + colg + 1);
                    v0 += a2A[k] * w0; v1 += a2A[k] * w1;
                    v2 += a2B[k] * w0; v3 += a2B[k] * w1;
                }
                vA[nt][0] = fmaxf(v0, 0.0f); vA[nt][1] = fmaxf(v1, 0.0f);
                vB[nt][0] = fmaxf(v2, 0.0f); vB[nt][1] = fmaxf(v3, 0.0f);
            }
            // store in A-fragment layout
            #pragma unroll
            for (int np = 0; np < 2; np++) {
                const int kkx = warp_n * 2 + np;
                const size_t off =
                    (((((size_t)blockIdx.y * 8 + kch_e) * 4 + kkx) * 8
                      + (warp_m * 2 + mt)) * 32 + lane) * 16;
                uint4 q;
                q.x = h2u(__floats2half2_rn(vA[2*np][0],   vA[2*np][1]));
                q.y = h2u(__floats2half2_rn(vB[2*np][0],   vB[2*np][1]));
                q.z = h2u(__floats2half2_rn(vA[2*np+1][0], vA[2*np+1][1]));
                q.w = h2u(__floats2half2_rn(vB[2*np+1][0], vB[2*np+1][1]));
                *(uint4*)((char*)outH + off) = q;
            }
        }
    } else {
        #pragma unroll
        for (int mt = 0; mt < 2; mt++) {
            const int rowA = m0 + warp_m * 32 + mt * 16 + qrow;
            const int rowB = rowA + 8;

            uint4 rf[2];
            #pragma unroll
            for (int np = 0; np < 2; np++) {
                const int kkx = warp_n * 2 + np;
                const size_t off =
                    (((((size_t)blockIdx.y * 8 + kch_e) * 4 + kkx) * 8
                      + (warp_m * 2 + mt)) * 32 + lane) * 16;
                rf[np] = *(const uint4*)((const char*)A + off);
            }
            const uint32_t rw[4][2] = {
                {rf[0].x, rf[0].y}, {rf[0].z, rf[0].w},
                {rf[1].x, rf[1].y}, {rf[1].z, rf[1].w}};

            float sA = 0.0f, sB = 0.0f;
            #pragma unroll
            for (int nt = 0; nt < 4; nt++) {
                const int colg = blockIdx.x * BN + warp_n * 32 + nt * 8 + qcol;
                const float b0 = __ldg(bias + colg), b1 = __ldg(bias + colg + 1);
                float2 hA = __half22float2(*(const __half2*)&rw[nt][0]);
                float2 hB = __half22float2(*(const __half2*)&rw[nt][1]);
                float v0 = c[mt][nt][0] + b0 + hA.x;
                float v1 = c[mt][nt][1] + b1 + hA.y;
                float v2 = c[mt][nt][2] + b0 + hB.x;
                float v3 = c[mt][nt][3] + b1 + hB.y;
                v0 = fmaxf(v0, 0.0f); v1 = fmaxf(v1, 0.0f);
                v2 = fmaxf(v2, 0.0f); v3 = fmaxf(v3, 0.0f);
                const float w0 = __ldg(w2 + colg), w1 = __ldg(w2 + colg + 1);
                sA += v0 * w0 + v1 * w1;
                sB += v2 * w0 + v3 * w1;
            }
            sA += __shfl_xor_sync(0xFFFFFFFFu, sA, 1);
            sA += __shfl_xor_sync(0xFFFFFFFFu, sA, 2);
            sB += __shfl_xor_sync(0xFFFFFFFFu, sB, 1);
            sB += __shfl_xor_sync(0xFFFFFFFFu, sB, 2);
            if ((lane & 3) == 0) {
                atomicAdd(dotOut + rowA, sA);
                atomicAdd(dotOut + rowB, sB);
            }
        }
    }
}

// ---------------------------------------------------------------------------
// Host orchestration
// ---------------------------------------------------------------------------
extern "C" void kernel_launch(void* const* d_in, const int* in_sizes, int n_in,
                              void* d_out, int out_size)
{
    const float* latent = (const float*)d_in[0];
    const float* rp     = (const float*)d_in[1];
    const float* w1[3] = {(const float*)d_in[2],  (const float*)d_in[8],  (const float*)d_in[14]};
    const float* b1[3] = {(const float*)d_in[3],  (const float*)d_in[9],  (const float*)d_in[15]};
    const float* wr[3] = {(const float*)d_in[4],  (const float*)d_in[10], (const float*)d_in[16]};
    const float* br[3] = {(const float*)d_in[5],  (const float*)d_in[11], (const float*)d_in[17]};
    const float* w2[3] = {(const float*)d_in[6],  (const float*)d_in[12], (const float*)d_in[18]};
    const float* b2[3] = {(const float*)d_in[7],  (const float*)d_in[13], (const float*)d_in[19]};

    float *feat, *std1, *std2;
    __half *lat, *h, *w1T, *wrT;
    cudaGetSymbolAddress((void**)&feat, g_feat);
    cudaGetSymbolAddress((void**)&lat,  g_lat);
    cudaGetSymbolAddress((void**)&h,    g_h);
    cudaGetSymbolAddress((void**)&std1, g_std1);
    cudaGetSymbolAddress((void**)&std2, g_std2);
    cudaGetSymbolAddress((void**)&w1T,  g_w1T);
    cudaGetSymbolAddress((void**)&wrT,  g_wrT);

    float* out = (float*)d_out;

    cudaFuncSetAttribute(gemm_mma_kernel<0>, cudaFuncAttributeMaxDynamicSharedMemorySize, SMEM_TOTAL);
    cudaFuncSetAttribute(gemm_mma_kernel<1>, cudaFuncAttributeMaxDynamicSharedMemorySize, SMEM_TOTAL);

    const dim3 ggrid(FD / BN, MROWS / BM);   // (8, 256)

    conv_frag_kernel<<<MROWS * FD / 8 / 256, 256>>>(latent, lat);
    knn_feat_kernel<<<dim3(NPTS / 256, BATCH), 256>>>(rp, feat);

    const float* stdprev[3] = {nullptr, std1, std2};
    const float* a2s[3]     = {feat, std1, std2};
    const int    k2s[3]     = {12, 1, 1};
    float*       stdout_[3] = {std1, std2, out};

    for (int s = 0; s < 3; s++) {
        transW_frag_kernel<<<FD * FD / 8 / 256, 256>>>(w1[s], w1T);
        gemm_mma_kernel<0><<<ggrid, 256, SMEM_TOTAL>>>(
            lat, w1T, b1[s],
            a2s[s], k2s[s], w1[s] + (size_t)FD * FD,
            h, nullptr, nullptr);
        transW_frag_kernel<<<FD * FD / 8 / 256, 256>>>(wr[s], wrT);
        init_out_kernel<<<MROWS / 256, 256>>>(stdprev[s], b2[s], stdout_[s]);
        gemm_mma_kernel<1><<<ggrid, 256, SMEM_TOTAL>>>(
            h, wrT, br[s],
            nullptr, 0, nullptr,
            nullptr, w2[s], stdout_[s]);
    }
}

// round 16
// speedup vs baseline: 1.5310x; 1.0694x over previous
#include <cuda_runtime.h>
#include <cuda_fp16.h>
#include <cstdint>

#define BATCH 8
#define NPTS  4096
#define MROWS 32768
#define FD    512

#define BM 128
#define BN 128
#define MBLK_STRIDE (8 * 16384)   // fragment layout: 8 k-chunks per 128-row/col block

// ---------------------------------------------------------------------------
// Device scratch (fragment-layout fp16 operands)
// ---------------------------------------------------------------------------
__device__ float  g_feat[MROWS * 12];
__device__ __half g_lat[MROWS * FD];    // A-fragment layout
__device__ __half g_h[MROWS * FD];      // A-fragment layout
__device__ float  g_std1[MROWS];
__device__ float  g_std2[MROWS];
__device__ __half g_w1T[FD * FD];       // B-fragment layout
__device__ __half g_wrT[FD * FD];       // B-fragment layout

// ---------------------------------------------------------------------------
// Helpers
// ---------------------------------------------------------------------------
__device__ __forceinline__ void mma_f16(float* c, const uint32_t* a, const uint32_t* b) {
    asm volatile(
        "mma.sync.aligned.m16n8k16.row.col.f32.f16.f16.f32 "
        "{%0,%1,%2,%3}, {%4,%5,%6,%7}, {%8,%9}, {%0,%1,%2,%3};"
        : "+f"(c[0]), "+f"(c[1]), "+f"(c[2]), "+f"(c[3])
        : "r"(a[0]), "r"(a[1]), "r"(a[2]), "r"(a[3]), "r"(b[0]), "r"(b[1]));
}

__device__ __forceinline__ uint32_t h2u(__half2 h) { return *(uint32_t*)&h; }

// ---------------------------------------------------------------------------
// kNN + local covariance
// ---------------------------------------------------------------------------
__global__ __launch_bounds__(256) void knn_feat_kernel(
    const float* __restrict__ rp, float* __restrict__ feat)
{
    __shared__ float px[NPTS], py[NPTS], pz[NPTS];
    const int b = blockIdx.y;
    const float* base = rp + b * 3 * NPTS;
    for (int i = threadIdx.x; i < NPTS; i += 256) {
        px[i] = base[i]; py[i] = base[NPTS + i]; pz[i] = base[2 * NPTS + i];
    }
    __syncthreads();

    const int n = blockIdx.x * 256 + threadIdx.x;
    const float xi = px[n], yi = py[n], zi = pz[n];
    const float xxi = xi * xi + yi * yi + zi * zi;

    float bestv = -1e30f; int bestj = 0;
    for (int j = 0; j < NPTS; j++) {
        const float xj = px[j], yj = py[j], zj = pz[j];
        const float d = 2.0f * (xi * xj + yi * yj + zi * zj) - xxi - (xj * xj + yj * yj + zj * zj);
        if (j != n && d > bestv) { bestv = d; bestj = j; }
    }
    const float nx = px[bestj], ny = py[bestj], nz = pz[bestj];
    float* f = feat + (size_t)(b * NPTS + n) * 12;
    f[0] = xi;      f[1] = yi;      f[2] = zi;
    f[3] = xi * nx; f[4] = xi * ny; f[5] = xi * nz;
    f[6] = yi * nx; f[7] = yi * ny; f[8] = yi * nz;
    f[9] = zi * nx; f[10] = zi * ny; f[11] = zi * nz;
}

// ---------------------------------------------------------------------------
// latent fp32 [m][k] -> A-fragment fp16 layout
// unit u = ((((mblk*8+kch)*4+kk)*8+mtb)*32+lane)
//   m = mblk*128 + mtb*16 + lane/4 ; k = kch*64 + kk*16 + (lane%4)*2
//   {x:(m,k) y:(m+8,k) z:(m,k+8) w:(m+8,k+8)}
// ---------------------------------------------------------------------------
__global__ __launch_bounds__(256) void conv_frag_kernel(
    const float* __restrict__ x, __half* __restrict__ o)
{
    const int u = blockIdx.x * 256 + threadIdx.x;
    const int lane = u & 31, mtb = (u >> 5) & 7, kk = (u >> 8) & 3;
    const int kch = (u >> 10) & 7, mblk = u >> 13;
    const int m = mblk * 128 + mtb * 16 + (lane >> 2);
    const int k = kch * 64 + kk * 16 + (lane & 3) * 2;
    const float* s0 = x + (size_t)m * FD + k;
    const float* s1 = s0 + 8 * FD;
    float2 f00 = *(const float2*)(s0);
    float2 f10 = *(const float2*)(s1);
    float2 f01 = *(const float2*)(s0 + 8);
    float2 f11 = *(const float2*)(s1 + 8);
    uint4 q;
    q.x = h2u(__floats2half2_rn(f00.x, f00.y));
    q.y = h2u(__floats2half2_rn(f10.x, f10.y));
    q.z = h2u(__floats2half2_rn(f01.x, f01.y));
    q.w = h2u(__floats2half2_rn(f11.x, f11.y));
    *(uint4*)((char*)o + (size_t)u * 16) = q;
}

// ---------------------------------------------------------------------------
// W fp32 [k][n] -> B-fragment fp16 layout
// ---------------------------------------------------------------------------
__global__ __launch_bounds__(256) void transW_frag_kernel(
    const float* __restrict__ W, __half* __restrict__ o)
{
    const int u = blockIdx.x * 256 + threadIdx.x;
    const int lane = u & 31, cb = (u >> 5) & 7, kk = (u >> 8) & 3;
    const int kch = (u >> 10) & 7, nblk = u >> 13;
    const int n = nblk * 128 + cb * 16 + (lane >> 2);
    const int k = kch * 64 + kk * 16 + (lane & 3) * 2;
    const float* s = W + (size_t)k * FD + n;
    uint4 q;
    q.x = h2u(__floats2half2_rn(s[0],          s[FD]));
    q.y = h2u(__floats2half2_rn(s[8 * FD],     s[9 * FD]));
    q.z = h2u(__floats2half2_rn(s[8],          s[FD + 8]));
    q.w = h2u(__floats2half2_rn(s[8 * FD + 8], s[9 * FD + 8]));
    *(uint4*)((char*)o + (size_t)u * 16) = q;
}

// ---------------------------------------------------------------------------
// out[row] = (prev ? prev[row] : 0) + b2[0]
// ---------------------------------------------------------------------------
__global__ __launch_bounds__(256) void init_out_kernel(
    const float* __restrict__ prev, const float* __restrict__ b2, float* __restrict__ out)
{
    const int i = blockIdx.x * 256 + threadIdx.x;
    out[i] = (prev ? prev[i] : 0.0f) + b2[0];
}

// ---------------------------------------------------------------------------
// Pure-LDG fp16 mma.sync GEMM. BM=128 x BN=128, 8 warps (4 warp_m x 2 warp_n),
// warp tile 32x64. No shared memory, no barriers — both operands streamed
// from fragment-layout gmem with register double buffering.
//  MODE 0:  H = relu(C + A2@Wtail + bias) -> outH (A-fragment layout)
//  MODE 1:  v = relu(C + A + bias); atomicAdd(dotOut, v@w2)
// ---------------------------------------------------------------------------
template <int MODE>
__global__ __launch_bounds__(256, 2) void gemm_mma_kernel(
    const __half* __restrict__ A,       // A-fragment layout
    const __half* __restrict__ B,       // B-fragment layout
    const float* __restrict__ bias,
    const float* __restrict__ A2, const int K2, const float* __restrict__ Wtail,
    __half* __restrict__ outH,
    const float* __restrict__ w2, float* __restrict__ dotOut)
{
    const int tid = threadIdx.x;
    const int warp = tid >> 5, lane = tid & 31;
    const int warp_m = warp >> 1;          // 0..3 -> 32 rows each
    const int warp_n = warp & 1;           // 0..1 -> 64 cols each
    const int m0 = blockIdx.y * BM;

    const char* Ab = (const char*)A + (size_t)blockIdx.y * MBLK_STRIDE
                     + (uint32_t)(((warp_m * 2) * 32 + lane) * 16);
    const char* Bb = (const char*)B + (size_t)blockIdx.x * MBLK_STRIDE
                     + (uint32_t)(((warp_n * 4) * 32 + lane) * 16);

    float c[2][8][4];
    #pragma unroll
    for (int i = 0; i < 2; i++)
        #pragma unroll
        for (int j = 0; j < 8; j++)
            #pragma unroll
            for (int q = 0; q < 4; q++) c[i][j][q] = 0.0f;

    uint4 aF[2][2], bF[2][4];

    auto ldstep = [&](int ks, int buf) {
        const uint32_t o = (uint32_t)ks * 4096;
        aF[buf][0] = __ldg((const uint4*)(Ab + o));
        aF[buf][1] = __ldg((const uint4*)(Ab + o + 512));
        #pragma unroll
        for (int cb = 0; cb < 4; cb++)
            bF[buf][cb] = __ldg((const uint4*)(Bb + o + cb * 512));
    };

    ldstep(0, 0);

    #pragma unroll 2
    for (int ks = 0; ks < 32; ks++) {
        const int cur = ks & 1;
        if (ks < 31) ldstep(ks + 1, cur ^ 1);
        #pragma unroll
        for (int mt = 0; mt < 2; mt++) {
            const uint32_t a[4] = {aF[cur][mt].x, aF[cur][mt].y, aF[cur][mt].z, aF[cur][mt].w};
            #pragma unroll
            for (int cb = 0; cb < 4; cb++) {
                const uint32_t lo[2] = {bF[cur][cb].x, bF[cur][cb].y};
                const uint32_t hi[2] = {bF[cur][cb].z, bF[cur][cb].w};
                mma_f16(c[mt][2 * cb],     a, lo);
                mma_f16(c[mt][2 * cb + 1], a, hi);
            }
        }
    }

    // ---- epilogue ----
    const int qrow = lane >> 2;            // 0..7
    const int qcol = (lane & 3) * 2;       // 0,2,4,6
    const int kch_e = blockIdx.x * 2 + warp_n;   // k-chunk of warp's 64 cols

    if (MODE == 0) {
        #pragma unroll
        for (int mt = 0; mt < 2; mt++) {
            const int rowA = m0 + warp_m * 32 + mt * 16 + qrow;
            const int rowB = rowA + 8;
            const int mtb = warp_m * 2 + mt;

            float a2A[12], a2B[12];
            for (int k = 0; k < K2; k++) {
                a2A[k] = __ldg(A2 + (size_t)rowA * K2 + k);
                a2B[k] = __ldg(A2 + (size_t)rowB * K2 + k);
            }

            #pragma unroll
            for (int cb = 0; cb < 4; cb++) {
                float v[2][4];   // [which nt of pair][q]
                #pragma unroll
                for (int p = 0; p < 2; p++) {
                    const int nt = 2 * cb + p;
                    const int colg = blockIdx.x * BN + warp_n * 64 + cb * 16 + p * 8 + qcol;
                    const float b0 = __ldg(bias + colg), b1 = __ldg(bias + colg + 1);
                    float v0 = c[mt][nt][0] + b0, v1 = c[mt][nt][1] + b1;
                    float v2 = c[mt][nt][2] + b0, v3 = c[mt][nt][3] + b1;
                    for (int k = 0; k < K2; k++) {
                        const float w0 = __ldg(Wtail + (size_t)k * FD + colg);
                        const float w1 = __ldg(Wtail + (size_t)k * FD + colg + 1);
                        v0 += a2A[k] * w0; v1 += a2A[k] * w1;
                        v2 += a2B[k] * w0; v3 += a2B[k] * w1;
                    }
                    v[p][0] = fmaxf(v0, 0.0f); v[p][1] = fmaxf(v1, 0.0f);
                    v[p][2] = fmaxf(v2, 0.0f); v[p][3] = fmaxf(v3, 0.0f);
                }
                // store unit: x=(m,k) y=(m+8,k) z=(m,k+8) w=(m+8,k+8)
                const size_t off =
                    (((((size_t)blockIdx.y * 8 + kch_e) * 4 + cb) * 8 + mtb) * 32 + lane) * 16;
                uint4 q;
                q.x = h2u(__floats2half2_rn(v[0][0], v[0][1]));
                q.y = h2u(__floats2half2_rn(v[0][2], v[0][3]));
                q.z = h2u(__floats2half2_rn(v[1][0], v[1][1]));
                q.w = h2u(__floats2half2_rn(v[1][2], v[1][3]));
                *(uint4*)((char*)outH + off) = q;
            }
        }
    } else {
        #pragma unroll
        for (int mt = 0; mt < 2; mt++) {
            const int rowA = m0 + warp_m * 32 + mt * 16 + qrow;
            const int rowB = rowA + 8;
            const int mtb = warp_m * 2 + mt;
            float sA = 0.0f, sB = 0.0f;

            #pragma unroll
            for (int cb = 0; cb < 4; cb++) {
                const size_t off =
                    (((((size_t)blockIdx.y * 8 + kch_e) * 4 + cb) * 8 + mtb) * 32 + lane) * 16;
                const uint4 rf = *(const uint4*)((const char*)A + off);
                const uint32_t rw[2][2] = {{rf.x, rf.y}, {rf.z, rf.w}};

                #pragma unroll
                for (int p = 0; p < 2; p++) {
                    const int nt = 2 * cb + p;
                    const int colg = blockIdx.x * BN + warp_n * 64 + cb * 16 + p * 8 + qcol;
                    const float b0 = __ldg(bias + colg), b1 = __ldg(bias + colg + 1);
                    float2 hA = __half22float2(*(const __half2*)&rw[p][0]);
                    float2 hB = __half22float2(*(const __half2*)&rw[p][1]);
                    float v0 = c[mt][nt][0] + b0 + hA.x;
                    float v1 = c[mt][nt][1] + b1 + hA.y;
                    float v2 = c[mt][nt][2] + b0 + hB.x;
                    float v3 = c[mt][nt][3] + b1 + hB.y;
                    v0 = fmaxf(v0, 0.0f); v1 = fmaxf(v1, 0.0f);
                    v2 = fmaxf(v2, 0.0f); v3 = fmaxf(v3, 0.0f);
                    const float w0 = __ldg(w2 + colg), w1 = __ldg(w2 + colg + 1);
                    sA += v0 * w0 + v1 * w1;
                    sB += v2 * w0 + v3 * w1;
                }
            }
            sA += __shfl_xor_sync(0xFFFFFFFFu, sA, 1);
            sA += __shfl_xor_sync(0xFFFFFFFFu, sA, 2);
            sB += __shfl_xor_sync(0xFFFFFFFFu, sB, 1);
            sB += __shfl_xor_sync(0xFFFFFFFFu, sB, 2);
            if ((lane & 3) == 0) {
                atomicAdd(dotOut + rowA, sA);
                atomicAdd(dotOut + rowB, sB);
            }
        }
    }
}

// ---------------------------------------------------------------------------
// Host orchestration
// ---------------------------------------------------------------------------
extern "C" void kernel_launch(void* const* d_in, const int* in_sizes, int n_in,
                              void* d_out, int out_size)
{
    const float* latent = (const float*)d_in[0];
    const float* rp     = (const float*)d_in[1];
    const float* w1[3] = {(const float*)d_in[2],  (const float*)d_in[8],  (const float*)d_in[14]};
    const float* b1[3] = {(const float*)d_in[3],  (const float*)d_in[9],  (const float*)d_in[15]};
    const float* wr[3] = {(const float*)d_in[4],  (const float*)d_in[10], (const float*)d_in[16]};
    const float* br[3] = {(const float*)d_in[5],  (const float*)d_in[11], (const float*)d_in[17]};
    const float* w2[3] = {(const float*)d_in[6],  (const float*)d_in[12], (const float*)d_in[18]};
    const float* b2[3] = {(const float*)d_in[7],  (const float*)d_in[13], (const float*)d_in[19]};

    float *feat, *std1, *std2;
    __half *lat, *h, *w1T, *wrT;
    cudaGetSymbolAddress((void**)&feat, g_feat);
    cudaGetSymbolAddress((void**)&lat,  g_lat);
    cudaGetSymbolAddress((void**)&h,    g_h);
    cudaGetSymbolAddress((void**)&std1, g_std1);
    cudaGetSymbolAddress((void**)&std2, g_std2);
    cudaGetSymbolAddress((void**)&w1T,  g_w1T);
    cudaGetSymbolAddress((void**)&wrT,  g_wrT);

    float* out = (float*)d_out;

    const dim3 ggrid(FD / BN, MROWS / BM);   // (4, 256)

    conv_frag_kernel<<<MROWS * FD / 8 / 256, 256>>>(latent, lat);
    knn_feat_kernel<<<dim3(NPTS / 256, BATCH), 256>>>(rp, feat);

    const float* stdprev[3] = {nullptr, std1, std2};
    const float* a2s[3]     = {feat, std1, std2};
    const int    k2s[3]     = {12, 1, 1};
    float*       stdout_[3] = {std1, std2, out};

    for (int s = 0; s < 3; s++) {
        transW_frag_kernel<<<FD * FD / 8 / 256, 256>>>(w1[s], w1T);
        gemm_mma_kernel<0><<<ggrid, 256>>>(
            lat, w1T, b1[s],
            a2s[s], k2s[s], w1[s] + (size_t)FD * FD,
            h, nullptr, nullptr);
        transW_frag_kernel<<<FD * FD / 8 / 256, 256>>>(wr[s], wrT);
        init_out_kernel<<<MROWS / 256, 256>>>(stdprev[s], b2[s], stdout_[s]);
        gemm_mma_kernel<1><<<ggrid, 256>>>(
            h, wrT, br[s],
            nullptr, 0, nullptr,
            nullptr, w2[s], stdout_[s]);
    }
}

// round 17
// speedup vs baseline: 1.6270x; 1.0627x over previous
#include <cuda_runtime.h>
#include <cuda_fp16.h>
#include <cstdint>

#define BATCH 8
#define NPTS  4096
#define MROWS 32768
#define FD    512

#define BM 128
#define BN 128
#define MBLK_STRIDE (8 * 16384)   // fragment layout: 8 k-chunks per 128-row/col block

// ---------------------------------------------------------------------------
// Device scratch (fragment-layout fp16 operands)
// ---------------------------------------------------------------------------
__device__ float  g_feat[MROWS * 12];
__device__ __half g_lat[MROWS * FD];    // A-fragment layout
__device__ __half g_h[MROWS * FD];      // A-fragment layout
__device__ __half g_tail[MROWS * FD];   // A-fragment layout: feat @ w1_tail
__device__ float  g_std1[MROWS];
__device__ float  g_std2[MROWS];
__device__ __half g_w1T[FD * FD];       // B-fragment layout
__device__ __half g_wrT[FD * FD];       // B-fragment layout

// ---------------------------------------------------------------------------
// Helpers
// ---------------------------------------------------------------------------
__device__ __forceinline__ void mma_f16(float* c, const uint32_t* a, const uint32_t* b) {
    asm volatile(
        "mma.sync.aligned.m16n8k16.row.col.f32.f16.f16.f32 "
        "{%0,%1,%2,%3}, {%4,%5,%6,%7}, {%8,%9}, {%0,%1,%2,%3};"
        : "+f"(c[0]), "+f"(c[1]), "+f"(c[2]), "+f"(c[3])
        : "r"(a[0]), "r"(a[1]), "r"(a[2]), "r"(a[3]), "r"(b[0]), "r"(b[1]));
}

__device__ __forceinline__ uint32_t h2u(__half2 h) { return *(uint32_t*)&h; }

// ---------------------------------------------------------------------------
// kNN + local covariance
// ---------------------------------------------------------------------------
__global__ __launch_bounds__(256) void knn_feat_kernel(
    const float* __restrict__ rp, float* __restrict__ feat)
{
    __shared__ float px[NPTS], py[NPTS], pz[NPTS];
    const int b = blockIdx.y;
    const float* base = rp + b * 3 * NPTS;
    for (int i = threadIdx.x; i < NPTS; i += 256) {
        px[i] = base[i]; py[i] = base[NPTS + i]; pz[i] = base[2 * NPTS + i];
    }
    __syncthreads();

    const int n = blockIdx.x * 256 + threadIdx.x;
    const float xi = px[n], yi = py[n], zi = pz[n];
    const float xxi = xi * xi + yi * yi + zi * zi;

    float bestv = -1e30f; int bestj = 0;
    for (int j = 0; j < NPTS; j++) {
        const float xj = px[j], yj = py[j], zj = pz[j];
        const float d = 2.0f * (xi * xj + yi * yj + zi * zj) - xxi - (xj * xj + yj * yj + zj * zj);
        if (j != n && d > bestv) { bestv = d; bestj = j; }
    }
    const float nx = px[bestj], ny = py[bestj], nz = pz[bestj];
    float* f = feat + (size_t)(b * NPTS + n) * 12;
    f[0] = xi;      f[1] = yi;      f[2] = zi;
    f[3] = xi * nx; f[4] = xi * ny; f[5] = xi * nz;
    f[6] = yi * nx; f[7] = yi * ny; f[8] = yi * nz;
    f[9] = zi * nx; f[10] = zi * ny; f[11] = zi * nz;
}

// ---------------------------------------------------------------------------
// latent fp32 [m][k] -> A-fragment fp16 layout
// unit u = ((((mblk*8+kch)*4+kk)*8+mtb)*32+lane)
//   m = mblk*128 + mtb*16 + lane/4 ; k = kch*64 + kk*16 + (lane%4)*2
//   {x:(m,k) y:(m+8,k) z:(m,k+8) w:(m+8,k+8)}
// ---------------------------------------------------------------------------
__global__ __launch_bounds__(256) void conv_frag_kernel(
    const float* __restrict__ x, __half* __restrict__ o)
{
    const int u = blockIdx.x * 256 + threadIdx.x;
    const int lane = u & 31, mtb = (u >> 5) & 7, kk = (u >> 8) & 3;
    const int kch = (u >> 10) & 7, mblk = u >> 13;
    const int m = mblk * 128 + mtb * 16 + (lane >> 2);
    const int k = kch * 64 + kk * 16 + (lane & 3) * 2;
    const float* s0 = x + (size_t)m * FD + k;
    const float* s1 = s0 + 8 * FD;
    float2 f00 = *(const float2*)(s0);
    float2 f10 = *(const float2*)(s1);
    float2 f01 = *(const float2*)(s0 + 8);
    float2 f11 = *(const float2*)(s1 + 8);
    uint4 q;
    q.x = h2u(__floats2half2_rn(f00.x, f00.y));
    q.y = h2u(__floats2half2_rn(f10.x, f10.y));
    q.z = h2u(__floats2half2_rn(f01.x, f01.y));
    q.w = h2u(__floats2half2_rn(f11.x, f11.y));
    *(uint4*)((char*)o + (size_t)u * 16) = q;
}

// ---------------------------------------------------------------------------
// tail[m][n] = sum_{k<12} feat[m][k] * Wtail[k][n]  -> A-fragment fp16 layout
// Same unit mapping as conv_frag (n plays the role of k there).
// ---------------------------------------------------------------------------
__global__ __launch_bounds__(256) void tail_frag_kernel(
    const float* __restrict__ feat, const float* __restrict__ Wtail,
    __half* __restrict__ o)
{
    const int u = blockIdx.x * 256 + threadIdx.x;
    const int lane = u & 31, mtb = (u >> 5) & 7, kk = (u >> 8) & 3;
    const int kch = (u >> 10) & 7, mblk = u >> 13;
    const int m = mblk * 128 + mtb * 16 + (lane >> 2);
    const int n = kch * 64 + kk * 16 + (lane & 3) * 2;

    const float* fA = feat + (size_t)m * 12;
    const float* fB = fA + 8 * 12;

    float v00 = 0.f, v01 = 0.f, v10 = 0.f, v11 = 0.f;   // (m,n) (m,n+1) (m+8,n) (m+8,n+1)
    float w00 = 0.f, w01 = 0.f, w10 = 0.f, w11 = 0.f;   // same at n+8, n+9
    #pragma unroll
    for (int k = 0; k < 12; k++) {
        const float a0 = fA[k], a1 = fB[k];
        const float* wr = Wtail + (size_t)k * FD + n;
        const float t0 = wr[0], t1 = wr[1], t8 = wr[8], t9 = wr[9];
        v00 += a0 * t0; v01 += a0 * t1;
        v10 += a1 * t0; v11 += a1 * t1;
        w00 += a0 * t8; w01 += a0 * t9;
        w10 += a1 * t8; w11 += a1 * t9;
    }
    uint4 q;
    q.x = h2u(__floats2half2_rn(v00, v01));
    q.y = h2u(__floats2half2_rn(v10, v11));
    q.z = h2u(__floats2half2_rn(w00, w01));
    q.w = h2u(__floats2half2_rn(w10, w11));
    *(uint4*)((char*)o + (size_t)u * 16) = q;
}

// ---------------------------------------------------------------------------
// W fp32 [k][n] -> B-fragment fp16 layout
// ---------------------------------------------------------------------------
__global__ __launch_bounds__(256) void transW_frag_kernel(
    const float* __restrict__ W, __half* __restrict__ o)
{
    const int u = blockIdx.x * 256 + threadIdx.x;
    const int lane = u & 31, cb = (u >> 5) & 7, kk = (u >> 8) & 3;
    const int kch = (u >> 10) & 7, nblk = u >> 13;
    const int n = nblk * 128 + cb * 16 + (lane >> 2);
    const int k = kch * 64 + kk * 16 + (lane & 3) * 2;
    const float* s = W + (size_t)k * FD + n;
    uint4 q;
    q.x = h2u(__floats2half2_rn(s[0],          s[FD]));
    q.y = h2u(__floats2half2_rn(s[8 * FD],     s[9 * FD]));
    q.z = h2u(__floats2half2_rn(s[8],          s[FD + 8]));
    q.w = h2u(__floats2half2_rn(s[8 * FD + 8], s[9 * FD + 8]));
    *(uint4*)((char*)o + (size_t)u * 16) = q;
}

// ---------------------------------------------------------------------------
// out[row] = (prev ? prev[row] : 0) + b2[0]
// ---------------------------------------------------------------------------
__global__ __launch_bounds__(256) void init_out_kernel(
    const float* __restrict__ prev, const float* __restrict__ b2, float* __restrict__ out)
{
    const int i = blockIdx.x * 256 + threadIdx.x;
    out[i] = (prev ? prev[i] : 0.0f) + b2[0];
}

// ---------------------------------------------------------------------------
// Pure-LDG fp16 mma.sync GEMM. BM=128 x BN=128, warp tile 32x64, no smem.
//  MODE 0:  H = relu(C + tailH? + A2@Wtail(K2) + bias) -> outH (fragment layout)
//  MODE 1:  v = relu(C + A + bias); atomicAdd(dotOut, v@w2)
// ---------------------------------------------------------------------------
template <int MODE>
__global__ __launch_bounds__(256, 2) void gemm_mma_kernel(
    const __half* __restrict__ A,       // A-fragment layout
    const __half* __restrict__ B,       // B-fragment layout
    const float* __restrict__ bias,
    const float* __restrict__ A2, const int K2, const float* __restrict__ Wtail,
    const __half* __restrict__ tailH,   // fragment-layout precomputed tail (or null)
    __half* __restrict__ outH,
    const float* __restrict__ w2, float* __restrict__ dotOut)
{
    const int tid = threadIdx.x;
    const int warp = tid >> 5, lane = tid & 31;
    const int warp_m = warp >> 1;          // 0..3 -> 32 rows each
    const int warp_n = warp & 1;           // 0..1 -> 64 cols each
    const int m0 = blockIdx.y * BM;

    const char* Ab = (const char*)A + (size_t)blockIdx.y * MBLK_STRIDE
                     + (uint32_t)(((warp_m * 2) * 32 + lane) * 16);
    const char* Bb = (const char*)B + (size_t)blockIdx.x * MBLK_STRIDE
                     + (uint32_t)(((warp_n * 4) * 32 + lane) * 16);

    float c[2][8][4];
    #pragma unroll
    for (int i = 0; i < 2; i++)
        #pragma unroll
        for (int j = 0; j < 8; j++)
            #pragma unroll
            for (int q = 0; q < 4; q++) c[i][j][q] = 0.0f;

    uint4 aF[2][2], bF[2][4];

    auto ldstep = [&](int ks, int buf) {
        const uint32_t o = (uint32_t)ks * 4096;
        aF[buf][0] = __ldg((const uint4*)(Ab + o));
        aF[buf][1] = __ldg((const uint4*)(Ab + o + 512));
        #pragma unroll
        for (int cb = 0; cb < 4; cb++)
            bF[buf][cb] = __ldg((const uint4*)(Bb + o + cb * 512));
    };

    ldstep(0, 0);

    #pragma unroll 2
    for (int ks = 0; ks < 32; ks++) {
        const int cur = ks & 1;
        if (ks < 31) ldstep(ks + 1, cur ^ 1);
        #pragma unroll
        for (int mt = 0; mt < 2; mt++) {
            const uint32_t a[4] = {aF[cur][mt].x, aF[cur][mt].y, aF[cur][mt].z, aF[cur][mt].w};
            #pragma unroll
            for (int cb = 0; cb < 4; cb++) {
                const uint32_t lo[2] = {bF[cur][cb].x, bF[cur][cb].y};
                const uint32_t hi[2] = {bF[cur][cb].z, bF[cur][cb].w};
                mma_f16(c[mt][2 * cb],     a, lo);
                mma_f16(c[mt][2 * cb + 1], a, hi);
            }
        }
    }

    // ---- epilogue ----
    const int qrow = lane >> 2;            // 0..7
    const int qcol = (lane & 3) * 2;       // 0,2,4,6
    const int kch_e = blockIdx.x * 2 + warp_n;   // k-chunk of warp's 64 cols

    if (MODE == 0) {
        #pragma unroll
        for (int mt = 0; mt < 2; mt++) {
            const int rowA = m0 + warp_m * 32 + mt * 16 + qrow;
            const int rowB = rowA + 8;
            const int mtb = warp_m * 2 + mt;

            float a2A = 0.f, a2B = 0.f;
            if (K2 == 1) {
                a2A = __ldg(A2 + rowA);
                a2B = __ldg(A2 + rowB);
            }

            #pragma unroll
            for (int cb = 0; cb < 4; cb++) {
                const size_t off =
                    (((((size_t)blockIdx.y * 8 + kch_e) * 4 + cb) * 8 + mtb) * 32 + lane) * 16;

                uint32_t tw[2][2] = {{0u, 0u}, {0u, 0u}};
                if (tailH) {
                    const uint4 tf = *(const uint4*)((const char*)tailH + off);
                    tw[0][0] = tf.x; tw[0][1] = tf.y;
                    tw[1][0] = tf.z; tw[1][1] = tf.w;
                }

                float v[2][4];
                #pragma unroll
                for (int p = 0; p < 2; p++) {
                    const int nt = 2 * cb + p;
                    const int colg = blockIdx.x * BN + warp_n * 64 + cb * 16 + p * 8 + qcol;
                    const float b0 = __ldg(bias + colg), b1 = __ldg(bias + colg + 1);
                    float v0 = c[mt][nt][0] + b0, v1 = c[mt][nt][1] + b1;
                    float v2 = c[mt][nt][2] + b0, v3 = c[mt][nt][3] + b1;
                    if (tailH) {
                        float2 tA = __half22float2(*(const __half2*)&tw[p][0]);
                        float2 tB = __half22float2(*(const __half2*)&tw[p][1]);
                        v0 += tA.x; v1 += tA.y;
                        v2 += tB.x; v3 += tB.y;
                    }
                    if (K2 == 1) {
                        const float w0 = __ldg(Wtail + colg);
                        const float w1 = __ldg(Wtail + colg + 1);
                        v0 += a2A * w0; v1 += a2A * w1;
                        v2 += a2B * w0; v3 += a2B * w1;
                    }
                    v[p][0] = fmaxf(v0, 0.0f); v[p][1] = fmaxf(v1, 0.0f);
                    v[p][2] = fmaxf(v2, 0.0f); v[p][3] = fmaxf(v3, 0.0f);
                }
                uint4 q;
                q.x = h2u(__floats2half2_rn(v[0][0], v[0][1]));
                q.y = h2u(__floats2half2_rn(v[0][2], v[0][3]));
                q.z = h2u(__floats2half2_rn(v[1][0], v[1][1]));
                q.w = h2u(__floats2half2_rn(v[1][2], v[1][3]));
                *(uint4*)((char*)outH + off) = q;
            }
        }
    } else {
        #pragma unroll
        for (int mt = 0; mt < 2; mt++) {
            const int rowA = m0 + warp_m * 32 + mt * 16 + qrow;
            const int rowB = rowA + 8;
            const int mtb = warp_m * 2 + mt;
            float sA = 0.0f, sB = 0.0f;

            #pragma unroll
            for (int cb = 0; cb < 4; cb++) {
                const size_t off =
                    (((((size_t)blockIdx.y * 8 + kch_e) * 4 + cb) * 8 + mtb) * 32 + lane) * 16;
                const uint4 rf = *(const uint4*)((const char*)A + off);
                const uint32_t rw[2][2] = {{rf.x, rf.y}, {rf.z, rf.w}};

                #pragma unroll
                for (int p = 0; p < 2; p++) {
                    const int nt = 2 * cb + p;
                    const int colg = blockIdx.x * BN + warp_n * 64 + cb * 16 + p * 8 + qcol;
                    const float b0 = __ldg(bias + colg), b1 = __ldg(bias + colg + 1);
                    float2 hA = __half22float2(*(const __half2*)&rw[p][0]);
                    float2 hB = __half22float2(*(const __half2*)&rw[p][1]);
                    float v0 = c[mt][nt][0] + b0 + hA.x;
                    float v1 = c[mt][nt][1] + b1 + hA.y;
                    float v2 = c[mt][nt][2] + b0 + hB.x;
                    float v3 = c[mt][nt][3] + b1 + hB.y;
                    v0 = fmaxf(v0, 0.0f); v1 = fmaxf(v1, 0.0f);
                    v2 = fmaxf(v2, 0.0f); v3 = fmaxf(v3, 0.0f);
                    const float w0 = __ldg(w2 + colg), w1 = __ldg(w2 + colg + 1);
                    sA += v0 * w0 + v1 * w1;
                    sB += v2 * w0 + v3 * w1;
                }
            }
            sA += __shfl_xor_sync(0xFFFFFFFFu, sA, 1);
            sA += __shfl_xor_sync(0xFFFFFFFFu, sA, 2);
            sB += __shfl_xor_sync(0xFFFFFFFFu, sB, 1);
            sB += __shfl_xor_sync(0xFFFFFFFFu, sB, 2);
            if ((lane & 3) == 0) {
                atomicAdd(dotOut + rowA, sA);
                atomicAdd(dotOut + rowB, sB);
            }
        }
    }
}

// ---------------------------------------------------------------------------
// Host orchestration
// ---------------------------------------------------------------------------
extern "C" void kernel_launch(void* const* d_in, const int* in_sizes, int n_in,
                              void* d_out, int out_size)
{
    const float* latent = (const float*)d_in[0];
    const float* rp     = (const float*)d_in[1];
    const float* w1[3] = {(const float*)d_in[2],  (const float*)d_in[8],  (const float*)d_in[14]};
    const float* b1[3] = {(const float*)d_in[3],  (const float*)d_in[9],  (const float*)d_in[15]};
    const float* wr[3] = {(const float*)d_in[4],  (const float*)d_in[10], (const float*)d_in[16]};
    const float* br[3] = {(const float*)d_in[5],  (const float*)d_in[11], (const float*)d_in[17]};
    const float* w2[3] = {(const float*)d_in[6],  (const float*)d_in[12], (const float*)d_in[18]};
    const float* b2[3] = {(const float*)d_in[7],  (const float*)d_in[13], (const float*)d_in[19]};

    float *feat, *std1, *std2;
    __half *lat, *h, *tail, *w1T, *wrT;
    cudaGetSymbolAddress((void**)&feat, g_feat);
    cudaGetSymbolAddress((void**)&lat,  g_lat);
    cudaGetSymbolAddress((void**)&h,    g_h);
    cudaGetSymbolAddress((void**)&tail, g_tail);
    cudaGetSymbolAddress((void**)&std1, g_std1);
    cudaGetSymbolAddress((void**)&std2, g_std2);
    cudaGetSymbolAddress((void**)&w1T,  g_w1T);
    cudaGetSymbolAddress((void**)&wrT,  g_wrT);

    float* out = (float*)d_out;

    const dim3 ggrid(FD / BN, MROWS / BM);   // (4, 256)
    const int frag_blocks = MROWS * FD / 8 / 256;   // 8192

    conv_frag_kernel<<<frag_blocks, 256>>>(latent, lat);
    knn_feat_kernel<<<dim3(NPTS / 256, BATCH), 256>>>(rp, feat);
    tail_frag_kernel<<<frag_blocks, 256>>>(feat, w1[0] + (size_t)FD * FD, tail);

    const float* stdprev[3] = {nullptr, std1, std2};
    const float* a2s[3]     = {nullptr, std1, std2};
    const int    k2s[3]     = {0, 1, 1};
    const __half* tails[3]  = {tail, nullptr, nullptr};
    float*       stdout_[3] = {std1, std2, out};

    for (int s = 0; s < 3; s++) {
        transW_frag_kernel<<<FD * FD / 8 / 256, 256>>>(w1[s], w1T);
        gemm_mma_kernel<0><<<ggrid, 256>>>(
            lat, w1T, b1[s],
            a2s[s], k2s[s], w1[s] + (size_t)FD * FD,
            tails[s], h, nullptr, nullptr);
        transW_frag_kernel<<<FD * FD / 8 / 256, 256>>>(wr[s], wrT);
        init_out_kernel<<<MROWS / 256, 256>>>(stdprev[s], b2[s], stdout_[s]);
        gemm_mma_kernel<1><<<ggrid, 256>>>(
            h, wrT, br[s],
            nullptr, 0, nullptr,
            nullptr, nullptr, w2[s], stdout_[s]);
    }
}